// round 4
// baseline (speedup 1.0000x reference)
#include <cuda_runtime.h>
#include <cuda_bf16.h>
#include <cstdint>

#define BB 2
#define HH 16
#define LL 2048
#define DD 64
#define TOPK 64
#define QT 16            // queries per CTA
#define KC 128           // keys per chunk
#define NCHUNK (LL/KC)   // 16
#define NTHREADS 256
#define NWARP 8
#define CAP 288          // candidate capacity per query
#define NLOAD 9          // CAP/32

// ---- smem offsets (bytes) ----
#define KBUF_OFF 0
#define KSTAGE   32768                     // khi 16K + klo 16K
#define QHI_OFF  65536
#define QLO_OFF  67584
#define CAND_OFF 69632                     // 16*288*8 = 36864
#define CNT_OFF  106496
#define THR_OFF  106560
#define SIDX_OFF 106624                    // 16*64*4
#define SVAL_OFF 110720                    // 16*64*4
#define SMEM_BYTES 114816

// ---- persistent bf16 hi/lo split of K (prep kernel output) ----
#define PREP_N (BB*HH*LL*DD/4)
__device__ __align__(16) uint2 KhiG[PREP_N];   // 8MB
__device__ __align__(16) uint2 KloG[PREP_N];   // 8MB

__device__ __forceinline__ uint32_t swz(uint32_t o) { return o ^ ((o >> 3) & 0x70u); }
__device__ __forceinline__ uint32_t sptr(const void* p) {
    return (uint32_t)__cvta_generic_to_shared(p);
}
__device__ __forceinline__ uint32_t pack_bf16(float a, float b) {
    __nv_bfloat162 t = __floats2bfloat162_rn(a, b);
    return *reinterpret_cast<uint32_t*>(&t);
}
__device__ __forceinline__ void cp_async16(uint32_t dst, const void* src) {
    asm volatile("cp.async.cg.shared.global [%0], [%1], 16;" :: "r"(dst), "l"(src));
}
__device__ __forceinline__ void ldsm_x4(uint32_t a[4], uint32_t addr) {
    asm volatile("ldmatrix.sync.aligned.m8n8.x4.shared.b16 {%0,%1,%2,%3}, [%4];"
                 : "=r"(a[0]), "=r"(a[1]), "=r"(a[2]), "=r"(a[3]) : "r"(addr));
}
__device__ __forceinline__ void ldsm_x2(uint32_t b[2], uint32_t addr) {
    asm volatile("ldmatrix.sync.aligned.m8n8.x2.shared.b16 {%0,%1}, [%2];"
                 : "=r"(b[0]), "=r"(b[1]) : "r"(addr));
}
__device__ __forceinline__ void mma16816(float c[4], const uint32_t a[4], const uint32_t b[2]) {
    asm volatile("mma.sync.aligned.m16n8k16.row.col.f32.bf16.bf16.f32 "
                 "{%0,%1,%2,%3}, {%4,%5,%6,%7}, {%8,%9}, {%0,%1,%2,%3};"
                 : "+f"(c[0]), "+f"(c[1]), "+f"(c[2]), "+f"(c[3])
                 : "r"(a[0]), "r"(a[1]), "r"(a[2]), "r"(a[3]), "r"(b[0]), "r"(b[1]));
}
// monotonic unsigned ordering of float bits
__device__ __forceinline__ unsigned ordbits(unsigned u) {
    return (u & 0x80000000u) ? ~u : (u | 0x80000000u);
}
__device__ __forceinline__ float invord(unsigned T) {
    unsigned u = (T & 0x80000000u) ? (T & 0x7FFFFFFFu) : ~T;
    return __uint_as_float(u);
}

// ---- prep: split K into bf16 hi + residual-lo ----
__global__ __launch_bounds__(256) void prep_k_kernel(const float4* __restrict__ K) {
    int i = blockIdx.x * 256 + threadIdx.x;
    float4 v = K[i];
    __nv_bfloat162 h01 = __floats2bfloat162_rn(v.x, v.y);
    __nv_bfloat162 h23 = __floats2bfloat162_rn(v.z, v.w);
    float l0 = v.x - __bfloat162float(h01.x);
    float l1 = v.y - __bfloat162float(h01.y);
    float l2 = v.z - __bfloat162float(h23.x);
    float l3 = v.w - __bfloat162float(h23.y);
    KhiG[i] = make_uint2(*reinterpret_cast<uint32_t*>(&h01),
                         *reinterpret_cast<uint32_t*>(&h23));
    KloG[i] = make_uint2(pack_bf16(l0, l1), pack_bf16(l2, l3));
}

// exact select on 32-bit keys over the candidate buffer of query q.
// final=false: compact buffer to keys >= rank-64 key, update cnt/thr.
// final=true : emit exactly TOPK (val,idx), ties broken by ascending idx,
//              then rank-sort by idx for deterministic reduction order.
__device__ __forceinline__ void select_q(uint2* cand, unsigned* cnt, float* thr,
                                         int* sidx, float* sval,
                                         int q, int lane, bool final_phase)
{
    const unsigned FULL = 0xFFFFFFFFu;
    uint2* buf = cand + q * CAP;
    const int n = min((int)cnt[q], CAP);
    uint2 e[NLOAD];
    unsigned key[NLOAD];
#pragma unroll
    for (int j = 0; j < NLOAD; j++) {
        int s = j * 32 + lane;
        if (s < n) { e[j] = buf[s]; key[j] = ordbits(e[j].x); }
        else       { e[j] = make_uint2(0u, 0u); key[j] = 0u; }
    }
    __syncwarp();
    // binary search: largest T with count(key >= T) >= TOPK
    unsigned lo = 0u, hi = 0xFFFFFFFFu;
    while (lo < hi) {
        unsigned mid = (unsigned)(((unsigned long long)lo + hi + 1ull) >> 1);
        int c = 0;
#pragma unroll
        for (int j = 0; j < NLOAD; j++)
            c += ((j * 32 + lane) < n) && (key[j] >= mid);
        c = (int)__reduce_add_sync(FULL, (unsigned)c);
        if (c >= TOPK) lo = mid; else hi = mid - 1u;
    }
    const unsigned T = lo;
    const unsigned ltm = (1u << lane) - 1u;

    if (!final_phase) {
        int base = 0;
#pragma unroll
        for (int j = 0; j < NLOAD; j++) {
            bool pv = ((j * 32 + lane) < n) && (key[j] >= T);
            unsigned m = __ballot_sync(FULL, pv);
            if (pv) buf[base + __popc(m & ltm)] = e[j];
            base += __popc(m);
        }
        if (lane == 0) { cnt[q] = (unsigned)base; thr[q] = invord(T); }
    } else {
        int* qi = sidx + q * 64;
        float* qv = sval + q * 64;
        int base = 0;
#pragma unroll
        for (int j = 0; j < NLOAD; j++) {
            bool pv = ((j * 32 + lane) < n) && (key[j] > T);
            unsigned m = __ballot_sync(FULL, pv);
            if (pv) {
                int p = base + __popc(m & ltm);
                qi[p] = (int)e[j].y;
                qv[p] = __uint_as_float(e[j].x);
            }
            base += __popc(m);
        }
        int need = TOPK - base;        // >= 1 by construction
        unsigned used = 0;
        for (int t = 0; t < need; t++) {
            unsigned best = 0xFFFFFFFFu; int bj = -1;
#pragma unroll
            for (int j = 0; j < NLOAD; j++) {
                bool pe = ((j * 32 + lane) < n) && (key[j] == T) && !((used >> j) & 1u);
                if (pe && e[j].y < best) { best = e[j].y; bj = j; }
            }
            unsigned m = __reduce_min_sync(FULL, best);
            if (best == m && bj >= 0) {
                used |= 1u << bj;
                qi[base + t] = (int)e[bj].y;
                qv[base + t] = __uint_as_float(e[bj].x);
            }
        }
        __syncwarp();
        // rank-sort by index (indices distinct -> perfect permutation)
        int i0 = qi[lane], i1 = qi[lane + 32];
        float v0 = qv[lane], v1 = qv[lane + 32];
        int r0 = 0, r1 = 0;
        for (int t = 0; t < 32; t++) {
            int u0 = __shfl_sync(FULL, i0, t);
            int u1 = __shfl_sync(FULL, i1, t);
            r0 += (u0 < i0) + (u1 < i0);
            r1 += (u0 < i1) + (u1 < i1);
        }
        __syncwarp();
        qi[r0] = i0; qv[r0] = v0;
        qi[r1] = i1; qv[r1] = v1;
        __syncwarp();
    }
}

__global__ __launch_bounds__(NTHREADS, 2)
void topk_attn_kernel(const float* __restrict__ Qg, const float* __restrict__ Vg,
                      float* __restrict__ Og)
{
    extern __shared__ char smem[];
    char*     qhi  = smem + QHI_OFF;
    char*     qlo  = smem + QLO_OFF;
    uint2*    cand = (uint2*)(smem + CAND_OFF);
    unsigned* cnt  = (unsigned*)(smem + CNT_OFF);
    float*    thr  = (float*)(smem + THR_OFF);
    int*      sidx = (int*)(smem + SIDX_OFF);
    float*    sval = (float*)(smem + SVAL_OFF);
    const uint32_t smem_u32 = sptr(smem);

    const int bh = blockIdx.x >> 7;
    const int qt = blockIdx.x & 127;
    const int q0 = qt * QT;
    const float* Qb = Qg + (size_t)bh * LL * DD;
    const float* Vb = Vg + (size_t)bh * LL * DD;

    const int tid  = threadIdx.x;
    const int lane = tid & 31;
    const int warp = tid >> 5;
    const unsigned FULL = 0xFFFFFFFFu;

    const char* khiG = (const char*)KhiG + ((size_t)bh * LL) * 128;
    const char* kloG = (const char*)KloG + ((size_t)bh * LL) * 128;
    auto issue_chunk = [&](int ch) {
        const uint32_t dbase = smem_u32 + KBUF_OFF + (ch & 1) * KSTAGE;
        const size_t gbase = (size_t)ch * KC * 128;
#pragma unroll
        for (int it = 0; it < 8; it++) {
            int fi = tid + it * NTHREADS;      // 0..2047
            int half = fi >> 10;               // 0=hi, 1=lo
            uint32_t off = (uint32_t)(fi & 1023) * 16;
            const char* src = (half ? kloG : khiG) + gbase + off;
            cp_async16(dbase + half * 16384 + swz(off), src);
        }
        asm volatile("cp.async.commit_group;" ::: "memory");
    };

    issue_chunk(0);

    // init counters: chunk 0 deterministically fills 128 candidates per query
    if (tid < QT) { cnt[tid] = 128u; thr[tid] = __int_as_float(0xFF800000); }

    // ---- load Q tile (fp32 -> bf16 hi/lo, swizzled) ----
    {
        int qrow = tid >> 4;          // 0..15
        int dc = (tid & 15) * 4;      // 0..60
        float4 qv4 = *(const float4*)(Qb + (size_t)(q0 + qrow) * DD + dc);
        __nv_bfloat162 h01 = __floats2bfloat162_rn(qv4.x, qv4.y);
        __nv_bfloat162 h23 = __floats2bfloat162_rn(qv4.z, qv4.w);
        float l0 = qv4.x - __bfloat162float(h01.x);
        float l1 = qv4.y - __bfloat162float(h01.y);
        float l2 = qv4.z - __bfloat162float(h23.x);
        float l3 = qv4.w - __bfloat162float(h23.y);
        uint32_t off = swz((uint32_t)(qrow * 128 + dc * 2));
        *(uint2*)(qhi + off) = make_uint2(*reinterpret_cast<uint32_t*>(&h01),
                                          *reinterpret_cast<uint32_t*>(&h23));
        *(uint2*)(qlo + off) = make_uint2(pack_bf16(l0, l1), pack_bf16(l2, l3));
    }
    __syncthreads();

    // ---- preload B fragments: both n-tiles (16 queries), 4 k-steps ----
    uint32_t Bh[2][4][2], Bl[2][4][2];
#pragma unroll
    for (int nt2 = 0; nt2 < 2; nt2++) {
        int qrow = nt2 * 8 + (lane & 7);
        int cb = ((lane >> 3) & 1) * 16;
#pragma unroll
        for (int ks = 0; ks < 4; ks++) {
            uint32_t off = swz((uint32_t)(qrow * 128 + ks * 32 + cb));
            ldsm_x2(Bh[nt2][ks], sptr(qhi + off));
            ldsm_x2(Bl[nt2][ks], sptr(qlo + off));
        }
    }
    // hoisted A-fragment offsets
    uint32_t aoff[4];
#pragma unroll
    for (int ks = 0; ks < 4; ks++)
        aoff[ks] = swz((uint32_t)((warp * 16 + (lane & 15)) * 128 +
                                  ks * 32 + ((lane >> 4) & 1) * 16));

    // ---- main loop ----
    for (int ch = 0; ch < NCHUNK; ch++) {
        asm volatile("cp.async.wait_group 0;" ::: "memory");
        __syncthreads();
        if (ch + 1 < NCHUNK) issue_chunk(ch + 1);

        const uint32_t khi = smem_u32 + KBUF_OFF + (ch & 1) * KSTAGE;
        const uint32_t klo = khi + 16384;

        float a0[4] = {0.f, 0.f, 0.f, 0.f};
        float a1[4] = {0.f, 0.f, 0.f, 0.f};
#pragma unroll
        for (int ks = 0; ks < 4; ks++) {
            uint32_t Ah[4], Al[4];
            ldsm_x4(Ah, khi + aoff[ks]);
            ldsm_x4(Al, klo + aoff[ks]);
            mma16816(a0, Ah, Bh[0][ks]);
            mma16816(a0, Al, Bh[0][ks]);
            mma16816(a0, Ah, Bl[0][ks]);
            mma16816(a1, Ah, Bh[1][ks]);
            mma16816(a1, Al, Bh[1][ks]);
            mma16816(a1, Ah, Bl[1][ks]);
        }

        const int r0 = warp * 16 + (lane >> 2);   // local key row within chunk
        const int qc = 2 * (lane & 3);
        if (ch == 0) {
            // deterministic direct placement (no atomics)
            cand[(qc    ) * CAP + r0    ] = make_uint2(__float_as_uint(a0[0]), (unsigned)r0);
            cand[(qc + 1) * CAP + r0    ] = make_uint2(__float_as_uint(a0[1]), (unsigned)r0);
            cand[(qc    ) * CAP + r0 + 8] = make_uint2(__float_as_uint(a0[2]), (unsigned)(r0 + 8));
            cand[(qc + 1) * CAP + r0 + 8] = make_uint2(__float_as_uint(a0[3]), (unsigned)(r0 + 8));
            cand[(qc + 8) * CAP + r0    ] = make_uint2(__float_as_uint(a1[0]), (unsigned)r0);
            cand[(qc + 9) * CAP + r0    ] = make_uint2(__float_as_uint(a1[1]), (unsigned)r0);
            cand[(qc + 8) * CAP + r0 + 8] = make_uint2(__float_as_uint(a1[2]), (unsigned)(r0 + 8));
            cand[(qc + 9) * CAP + r0 + 8] = make_uint2(__float_as_uint(a1[3]), (unsigned)(r0 + 8));
        } else {
            const int kr = ch * KC + r0;
#pragma unroll
            for (int u = 0; u < 8; u++) {
                float v = (u < 4) ? a0[u] : a1[u - 4];
                int q = qc + ((u < 4) ? 0 : 8) + (u & 1);
                int k = kr + ((u & 2) ? 8 : 0);
                if (v > thr[q]) {
                    unsigned p = atomicAdd(&cnt[q], 1u);
                    if (p < CAP) cand[q * CAP + p] =
                        make_uint2(__float_as_uint(v), (unsigned)k);
                }
            }
        }

        // doubling compaction schedule: threshold from S seen keys admits
        // ~64 expected appends over the next S keys (S*64/(S+1)), so
        // compact at seen = 128, 256, 512, 1024 -> slack 224 = ~20 sigma.
        if (ch == 0 || ch == 1 || ch == 3 || ch == 7) {
            __syncthreads();
            select_q(cand, cnt, thr, sidx, sval, warp,     lane, false);
            select_q(cand, cnt, thr, sidx, sval, warp + 8, lane, false);
            __syncthreads();
        }
    }
    __syncthreads();

    // ---- final: exact top-64, softmax, V gather (warp handles 2 queries) ----
#pragma unroll 1
    for (int qq = 0; qq < 2; qq++) {
        const int q = warp + qq * 8;
        select_q(cand, cnt, thr, sidx, sval, q, lane, true);

        const int* qi = sidx + q * 64;
        const float* qv = sval + q * 64;
        int   k0 = qi[lane],      k1 = qi[lane + 32];
        float v0 = qv[lane],      v1 = qv[lane + 32];
        float m = fmaxf(v0, v1);
#pragma unroll
        for (int o = 16; o; o >>= 1) m = fmaxf(m, __shfl_xor_sync(FULL, m, o));
        float e0 = __expf(v0 - m), e1 = __expf(v1 - m);
        float s = e0 + e1;
#pragma unroll
        for (int o = 16; o; o >>= 1) s += __shfl_xor_sync(FULL, s, o);
        float inv = 1.f / s;
        float w0 = e0 * inv, w1 = e1 * inv;

        float o0 = 0.f, o1 = 0.f;
#pragma unroll 8
        for (int i = 0; i < 32; i++) {
            float wa = __shfl_sync(FULL, w0, i); int ka = __shfl_sync(FULL, k0, i);
            float wb = __shfl_sync(FULL, w1, i); int kb = __shfl_sync(FULL, k1, i);
            const float* ra = Vb + (size_t)ka * DD;
            const float* rb = Vb + (size_t)kb * DD;
            o0 += wa * ra[lane];      o1 += wa * ra[lane + 32];
            o0 += wb * rb[lane];      o1 += wb * rb[lane + 32];
        }
        size_t ob = ((size_t)bh * LL + q0 + q) * DD;
        Og[ob + lane]      = o0;
        Og[ob + lane + 32] = o1;
    }
}

extern "C" void kernel_launch(void* const* d_in, const int* in_sizes, int n_in,
                              void* d_out, int out_size)
{
    (void)in_sizes; (void)n_in; (void)out_size;
    const float* Q = (const float*)d_in[0];
    const float* K = (const float*)d_in[1];
    const float* V = (const float*)d_in[2];
    float* O = (float*)d_out;

    prep_k_kernel<<<PREP_N / 256, 256>>>((const float4*)K);

    cudaFuncSetAttribute(topk_attn_kernel,
                         cudaFuncAttributeMaxDynamicSharedMemorySize, SMEM_BYTES);
    dim3 grid(BB * HH * (LL / QT));   // 4096 CTAs
    topk_attn_kernel<<<grid, NTHREADS, SMEM_BYTES>>>(Q, V, O);
}